// round 2
// baseline (speedup 1.0000x reference)
#include <cuda_runtime.h>
#include <cuda_bf16.h>

// ---------------------------------------------------------------------------
// SlabAttention: B=16, N=4096, C=384, H=12, hd=32, BH=192
//   qkv = x @ qkv_w^T ; q=relu(q); k=relu(k+pos); split heads
//   z_i = 1/(q_i . sum_j k_j + eps)
//   kv  = k^T v (per bh, 32x32)
//   out = (q @ kv) * z + depthwise5x5(v) + dwc_b
//   y   = out @ proj_w^T + proj_b
// ---------------------------------------------------------------------------

#define BATCH   16
#define NTOK    4096
#define CDIM    384
#define HEADS   12
#define HD      32
#define BH_TOT  (BATCH*HEADS)      // 192
#define M_TOT   (BATCH*NTOK)       // 65536
#define EPS     1e-6f

// scratch (device globals; allocation-free rule)
__device__ float g_q  [(size_t)BH_TOT * NTOK * HD];   // 100.7 MB
__device__ float g_k  [(size_t)BH_TOT * NTOK * HD];
__device__ float g_v  [(size_t)BH_TOT * NTOK * HD];
__device__ float g_pre[(size_t)M_TOT * CDIM];         // 100.7 MB
__device__ float g_ksum[BH_TOT * HD];
__device__ float g_kv  [BH_TOT * HD * HD];

// ---------------------------------------------------------------------------
// Kernel 1: qkv GEMM (M=65536, Nout=1152, K=384) with fused epilogue.
// C[m,j] = sum_k x[m,k] * qkv_w[j,k]
// 64x64 tile, BK=16, 256 threads, 4x4 per-thread microkernel.
// ---------------------------------------------------------------------------
__global__ __launch_bounds__(256) void qkv_gemm(const float* __restrict__ A,
                                                const float* __restrict__ W,
                                                const float* __restrict__ pos)
{
    __shared__ float As[16][65];
    __shared__ float Bs[16][65];

    const int tid = threadIdx.x;
    const int mB  = blockIdx.y * 64;
    const int jB  = blockIdx.x * 64;
    const int lm  = tid >> 2;        // 0..63  (row of the 64-wide tile to load)
    const int lk  = (tid & 3) * 4;   // 0,4,8,12 (k quad)
    const int ty  = tid >> 4;        // 0..15
    const int tx  = tid & 15;        // 0..15

    float acc[4][4];
#pragma unroll
    for (int i = 0; i < 4; i++)
#pragma unroll
        for (int j = 0; j < 4; j++) acc[i][j] = 0.f;

    for (int k0 = 0; k0 < CDIM; k0 += 16) {
        float4 av = *(const float4*)&A[(size_t)(mB + lm) * CDIM + k0 + lk];
        float4 bv = *(const float4*)&W[(size_t)(jB + lm) * CDIM + k0 + lk];
        As[lk + 0][lm] = av.x; As[lk + 1][lm] = av.y;
        As[lk + 2][lm] = av.z; As[lk + 3][lm] = av.w;
        Bs[lk + 0][lm] = bv.x; Bs[lk + 1][lm] = bv.y;
        Bs[lk + 2][lm] = bv.z; Bs[lk + 3][lm] = bv.w;
        __syncthreads();
#pragma unroll
        for (int kk = 0; kk < 16; kk++) {
            float a[4], b[4];
#pragma unroll
            for (int i = 0; i < 4; i++) a[i] = As[kk][ty * 4 + i];
#pragma unroll
            for (int j = 0; j < 4; j++) b[j] = Bs[kk][tx * 4 + j];
#pragma unroll
            for (int i = 0; i < 4; i++)
#pragma unroll
                for (int j = 0; j < 4; j++) acc[i][j] += a[i] * b[j];
        }
        __syncthreads();
    }

    // epilogue: part is uniform per block (jB multiple of 64; 384/64=6 blocks/part)
    const int part = jB / CDIM;                 // 0=q, 1=k, 2=v
#pragma unroll
    for (int i = 0; i < 4; i++) {
        const int m = mB + ty * 4 + i;
        const int b = m >> 12;                  // /4096
        const int n = m & 4095;
#pragma unroll
        for (int j = 0; j < 4; j++) {
            const int jj = jB + tx * 4 + j;
            const int c  = jj - part * CDIM;    // 0..383
            const int h  = c >> 5;
            const int d  = c & 31;
            const size_t o = (((size_t)(b * HEADS + h)) * NTOK + n) * HD + d;
            float val = acc[i][j];
            if (part == 0)      g_q[o] = fmaxf(val, 0.f);
            else if (part == 1) g_k[o] = fmaxf(val + pos[(size_t)n * CDIM + c], 0.f);
            else                g_v[o] = val;
        }
    }
}

// ---------------------------------------------------------------------------
// Kernel 2: ksum[bh,d] = sum_j k[bh,j,d]
// ---------------------------------------------------------------------------
__global__ __launch_bounds__(256) void ksum_kernel()
{
    const int bh = blockIdx.x;
    const int tid = threadIdx.x;
    const int d = tid & 31, g = tid >> 5;       // 8 row-groups
    __shared__ float s[256];
    const size_t base = (size_t)bh * NTOK * HD;
    float acc = 0.f;
    for (int j = g; j < NTOK; j += 8) acc += g_k[base + (size_t)j * HD + d];
    s[tid] = acc;
    __syncthreads();
    if (g == 0) {
        float t = 0.f;
#pragma unroll
        for (int gg = 0; gg < 8; gg++) t += s[gg * 32 + d];
        g_ksum[bh * HD + d] = t;
    }
}

// ---------------------------------------------------------------------------
// Kernel 3: kv[bh,c,d] = sum_j k[bh,j,c] * v[bh,j,d]   (32x32 per bh)
// ---------------------------------------------------------------------------
__global__ __launch_bounds__(256) void kv_kernel()
{
    const int bh = blockIdx.x;
    const int tid = threadIdx.x;
    const int d = tid & 31;
    const int cbase = (tid >> 5) * 4;           // 0,4,..,28
    __shared__ float sk[64 * 32];
    __shared__ float sv[64 * 32];
    const size_t base = (size_t)bh * NTOK * HD;
    float acc[4] = {0.f, 0.f, 0.f, 0.f};

    for (int j0 = 0; j0 < NTOK; j0 += 64) {
        for (int i = tid; i < 2048; i += 256) {
            sk[i] = g_k[base + (size_t)j0 * HD + i];
            sv[i] = g_v[base + (size_t)j0 * HD + i];
        }
        __syncthreads();
#pragma unroll 8
        for (int r = 0; r < 64; r++) {
            const float vv = sv[r * 32 + d];
#pragma unroll
            for (int q = 0; q < 4; q++) acc[q] += sk[r * 32 + cbase + q] * vv;
        }
        __syncthreads();
    }
#pragma unroll
    for (int q = 0; q < 4; q++)
        g_kv[bh * (HD * HD) + (cbase + q) * HD + d] = acc[q];
}

// ---------------------------------------------------------------------------
// Kernel 4: out = (q @ kv) * z + dwconv5x5(v) + dwc_b, written to g_pre
// in (B, N, C) layout. Block = 8 token rows x 32 channels, 256 threads.
// ---------------------------------------------------------------------------
__global__ __launch_bounds__(256) void attn_out(const float* __restrict__ dwc_w,
                                                const float* __restrict__ dwc_b)
{
    const int bh = blockIdx.y;
    const int rowblk = blockIdx.x;              // 0..511
    const int tid = threadIdx.x;
    const int r = tid >> 5, d = tid & 31;
    const int n = rowblk * 8 + r;

    __shared__ float skv[HD * HD];
    __shared__ float sksum[HD];
    __shared__ float sw[HD * 25];
    __shared__ float sq[8][HD];

    for (int i = tid; i < HD * HD; i += 256) skv[i] = g_kv[bh * (HD * HD) + i];
    if (tid < HD) sksum[tid] = g_ksum[bh * HD + tid];
    for (int i = tid; i < HD * 25; i += 256) sw[i] = dwc_w[i];

    const size_t base = (size_t)bh * NTOK * HD;
    sq[r][d] = g_q[base + (size_t)n * HD + d];
    __syncthreads();

    // z: warp = one token row, lane = channel
    float p = sq[r][d] * sksum[d];
#pragma unroll
    for (int off = 16; off; off >>= 1) p += __shfl_xor_sync(0xffffffffu, p, off);
    const float z = 1.f / (p + EPS);

    float o = 0.f;
#pragma unroll
    for (int c = 0; c < HD; c++) o += sq[r][c] * skv[c * HD + d];
    o *= z;

    // depthwise 5x5 (cross-correlation, pad 2), v laid out [bh, y*64+x, d]
    const int y = n >> 6, x = n & 63;
    float cv = dwc_b[d];
#pragma unroll
    for (int ky = 0; ky < 5; ky++) {
        const int yy = y + ky - 2;
        if ((unsigned)yy >= 64u) continue;
#pragma unroll
        for (int kx = 0; kx < 5; kx++) {
            const int xx = x + kx - 2;
            if ((unsigned)xx >= 64u) continue;
            cv += sw[d * 25 + ky * 5 + kx] *
                  g_v[base + (size_t)(yy * 64 + xx) * HD + d];
        }
    }

    const int b = bh / HEADS, h = bh % HEADS;
    g_pre[((size_t)(b * NTOK + n)) * CDIM + h * HD + d] = o + cv;
}

// ---------------------------------------------------------------------------
// Kernel 5: proj GEMM (M=65536, Nout=384, K=384) + bias -> d_out
// ---------------------------------------------------------------------------
__global__ __launch_bounds__(256) void proj_gemm(const float* __restrict__ W,
                                                 const float* __restrict__ bias,
                                                 float* __restrict__ out)
{
    __shared__ float As[16][65];
    __shared__ float Bs[16][65];

    const int tid = threadIdx.x;
    const int mB  = blockIdx.y * 64;
    const int jB  = blockIdx.x * 64;
    const int lm  = tid >> 2;
    const int lk  = (tid & 3) * 4;
    const int ty  = tid >> 4;
    const int tx  = tid & 15;

    float acc[4][4];
#pragma unroll
    for (int i = 0; i < 4; i++)
#pragma unroll
        for (int j = 0; j < 4; j++) acc[i][j] = 0.f;

    for (int k0 = 0; k0 < CDIM; k0 += 16) {
        float4 av = *(const float4*)&g_pre[(size_t)(mB + lm) * CDIM + k0 + lk];
        float4 bv = *(const float4*)&W[(size_t)(jB + lm) * CDIM + k0 + lk];
        As[lk + 0][lm] = av.x; As[lk + 1][lm] = av.y;
        As[lk + 2][lm] = av.z; As[lk + 3][lm] = av.w;
        Bs[lk + 0][lm] = bv.x; Bs[lk + 1][lm] = bv.y;
        Bs[lk + 2][lm] = bv.z; Bs[lk + 3][lm] = bv.w;
        __syncthreads();
#pragma unroll
        for (int kk = 0; kk < 16; kk++) {
            float a[4], b[4];
#pragma unroll
            for (int i = 0; i < 4; i++) a[i] = As[kk][ty * 4 + i];
#pragma unroll
            for (int j = 0; j < 4; j++) b[j] = Bs[kk][tx * 4 + j];
#pragma unroll
            for (int i = 0; i < 4; i++)
#pragma unroll
                for (int j = 0; j < 4; j++) acc[i][j] += a[i] * b[j];
        }
        __syncthreads();
    }

#pragma unroll
    for (int i = 0; i < 4; i++) {
        const int m = mB + ty * 4 + i;
#pragma unroll
        for (int j = 0; j < 4; j++) {
            const int jj = jB + tx * 4 + j;
            out[(size_t)m * CDIM + jj] = acc[i][j] + bias[jj];
        }
    }
}

// ---------------------------------------------------------------------------
extern "C" void kernel_launch(void* const* d_in, const int* in_sizes, int n_in,
                              void* d_out, int out_size)
{
    const float* x      = (const float*)d_in[0];
    const float* qkv_w  = (const float*)d_in[1];
    const float* pos    = (const float*)d_in[2];
    const float* dwc_w  = (const float*)d_in[3];
    const float* dwc_b  = (const float*)d_in[4];
    const float* proj_w = (const float*)d_in[5];
    const float* proj_b = (const float*)d_in[6];
    float* out = (float*)d_out;

    dim3 g1(3 * CDIM / 64, M_TOT / 64);   // 18 x 1024
    qkv_gemm<<<g1, 256>>>(x, qkv_w, pos);

    ksum_kernel<<<BH_TOT, 256>>>();
    kv_kernel<<<BH_TOT, 256>>>();

    dim3 g4(NTOK / 8, BH_TOT);            // 512 x 192
    attn_out<<<g4, 256>>>(dwc_w, dwc_b);

    dim3 g5(CDIM / 64, M_TOT / 64);       // 6 x 1024
    proj_gemm<<<g5, 256>>>(proj_w, proj_b, out);
}

// round 3
// speedup vs baseline: 2.1058x; 2.1058x over previous
#include <cuda_runtime.h>
#include <cuda_bf16.h>

// ---------------------------------------------------------------------------
// SlabAttention: B=16, N=4096, C=384, H=12, hd=32, BH=192
// Round 2: tf32 mma.sync GEMMs (qkv + proj), chunked kv+ksum with atomics.
// ---------------------------------------------------------------------------

#define BATCH   16
#define NTOK    4096
#define CDIM    384
#define HEADS   12
#define HD      32
#define BH_TOT  (BATCH*HEADS)      // 192
#define M_TOT   (BATCH*NTOK)       // 65536
#define EPS     1e-6f

#define LDA 136   // 128 + 8 pad (8-float pad -> conflict-free frag loads)
#define LDB 72    // 64 + 8 pad

// scratch (device globals; allocation-free rule)
__device__ float g_q  [(size_t)BH_TOT * NTOK * HD];
__device__ float g_k  [(size_t)BH_TOT * NTOK * HD];
__device__ float g_v  [(size_t)BH_TOT * NTOK * HD];
__device__ float g_pre[(size_t)M_TOT * CDIM];
__device__ float g_ksum[BH_TOT * HD];
__device__ float g_kv  [BH_TOT * HD * HD];

__device__ __forceinline__ float f2tf(float x) {
    asm("cvt.rna.tf32.f32 %0, %1;" : "=f"(x) : "f"(x));
    return x;
}

// D += A*B  (m16n8k8 tf32). a[4], b[2], c[4] per PTX fragment layout.
__device__ __forceinline__ void mma_tf32(float* c, const float* a, const float* b) {
    const unsigned* A = reinterpret_cast<const unsigned*>(a);
    const unsigned* B = reinterpret_cast<const unsigned*>(b);
    asm volatile(
        "mma.sync.aligned.m16n8k8.row.col.f32.tf32.tf32.f32 "
        "{%0,%1,%2,%3},{%4,%5,%6,%7},{%8,%9},{%0,%1,%2,%3};\n"
        : "+f"(c[0]), "+f"(c[1]), "+f"(c[2]), "+f"(c[3])
        : "r"(A[0]), "r"(A[1]), "r"(A[2]), "r"(A[3]), "r"(B[0]), "r"(B[1]));
}

// ---------------------------------------------------------------------------
// Kernel 1: qkv GEMM (M=65536, Nout=1152, K=384), tf32 tensor cores.
// BM=128, BN=64, BK=16, 256 threads (8 warps, 4M x 2N), warp tile 32x32.
// Fused epilogue: relu(q), relu(k+pos), head scatter.
// ---------------------------------------------------------------------------
__global__ __launch_bounds__(256) void qkv_gemm(const float* __restrict__ A,
                                                const float* __restrict__ W,
                                                const float* __restrict__ pos)
{
    __shared__ float As[16 * LDA];
    __shared__ float Bs[16 * LDB];

    const int tid  = threadIdx.x;
    const int mB   = blockIdx.y * 128;
    const int jB   = blockIdx.x * 64;
    const int lane = tid & 31;
    const int warp = tid >> 5;
    const int g    = lane >> 2;
    const int t    = lane & 3;
    const int wM   = (warp & 3) * 32;
    const int wN   = (warp >> 2) * 32;

    // loaders
    const int arow = tid >> 1;          // 0..127
    const int ak   = (tid & 1) * 8;     // k offset 0 or 8
    const int brow = tid >> 2;          // 0..63
    const int bk   = (tid & 3) * 4;     // k offset 0,4,8,12

    float acc[2][4][4];
#pragma unroll
    for (int i = 0; i < 2; i++)
#pragma unroll
        for (int j = 0; j < 4; j++)
#pragma unroll
            for (int l = 0; l < 4; l++) acc[i][j][l] = 0.f;

    for (int k0 = 0; k0 < CDIM; k0 += 16) {
        float4 av0 = *(const float4*)&A[(size_t)(mB + arow) * CDIM + k0 + ak];
        float4 av1 = *(const float4*)&A[(size_t)(mB + arow) * CDIM + k0 + ak + 4];
        float4 bv  = *(const float4*)&W[(size_t)(jB + brow) * CDIM + k0 + bk];

        As[(ak + 0) * LDA + arow] = f2tf(av0.x);
        As[(ak + 1) * LDA + arow] = f2tf(av0.y);
        As[(ak + 2) * LDA + arow] = f2tf(av0.z);
        As[(ak + 3) * LDA + arow] = f2tf(av0.w);
        As[(ak + 4) * LDA + arow] = f2tf(av1.x);
        As[(ak + 5) * LDA + arow] = f2tf(av1.y);
        As[(ak + 6) * LDA + arow] = f2tf(av1.z);
        As[(ak + 7) * LDA + arow] = f2tf(av1.w);
        Bs[(bk + 0) * LDB + brow] = f2tf(bv.x);
        Bs[(bk + 1) * LDB + brow] = f2tf(bv.y);
        Bs[(bk + 2) * LDB + brow] = f2tf(bv.z);
        Bs[(bk + 3) * LDB + brow] = f2tf(bv.w);
        __syncthreads();

#pragma unroll
        for (int ks = 0; ks < 16; ks += 8) {
            float a[2][4], b[4][2];
#pragma unroll
            for (int mt = 0; mt < 2; mt++) {
                const float* p0 = &As[(ks + t)     * LDA + wM + mt * 16 + g];
                const float* p1 = &As[(ks + t + 4) * LDA + wM + mt * 16 + g];
                a[mt][0] = p0[0]; a[mt][1] = p0[8];
                a[mt][2] = p1[0]; a[mt][3] = p1[8];
            }
#pragma unroll
            for (int nt = 0; nt < 4; nt++) {
                b[nt][0] = Bs[(ks + t)     * LDB + wN + nt * 8 + g];
                b[nt][1] = Bs[(ks + t + 4) * LDB + wN + nt * 8 + g];
            }
#pragma unroll
            for (int mt = 0; mt < 2; mt++)
#pragma unroll
                for (int nt = 0; nt < 4; nt++)
                    mma_tf32(acc[mt][nt], a[mt], b[nt]);
        }
        __syncthreads();
    }

    // epilogue (part uniform per block: 1152 = 18 blocks of 64; 6 per part)
    const int part = jB / CDIM;
#pragma unroll
    for (int mt = 0; mt < 2; mt++) {
#pragma unroll
        for (int nt = 0; nt < 4; nt++) {
            const int j = jB + wN + nt * 8 + 2 * t;
            const int c = j - part * CDIM;
            const int h = c >> 5;
            const int d = c & 31;
#pragma unroll
            for (int hh = 0; hh < 2; hh++) {
                const int m = mB + wM + mt * 16 + g + hh * 8;
                const int b_ = m >> 12;
                const int n  = m & 4095;
                float v0 = acc[mt][nt][hh * 2 + 0];
                float v1 = acc[mt][nt][hh * 2 + 1];
                const size_t o = (((size_t)(b_ * HEADS + h)) * NTOK + n) * HD + d;
                if (part == 0) {
                    *(float2*)&g_q[o] = make_float2(fmaxf(v0, 0.f), fmaxf(v1, 0.f));
                } else if (part == 1) {
                    v0 = fmaxf(v0 + pos[(size_t)n * CDIM + c],     0.f);
                    v1 = fmaxf(v1 + pos[(size_t)n * CDIM + c + 1], 0.f);
                    *(float2*)&g_k[o] = make_float2(v0, v1);
                } else {
                    *(float2*)&g_v[o] = make_float2(v0, v1);
                }
            }
        }
    }
}

// ---------------------------------------------------------------------------
// Kernel 1b: zero the accumulators for kv / ksum
// ---------------------------------------------------------------------------
__global__ __launch_bounds__(256) void zero_kv()
{
    const int i = blockIdx.x * 256 + threadIdx.x;
    if (i < BH_TOT * HD * HD) g_kv[i] = 0.f;
    if (i < BH_TOT * HD)      g_ksum[i] = 0.f;
}

// ---------------------------------------------------------------------------
// Kernel 2: kv[bh,c,d] += sum_{j in chunk} k[bh,j,c]*v[bh,j,d]; ksum fused.
// grid (192, 8): each block reduces 512 tokens, atomicAdd into globals.
// ---------------------------------------------------------------------------
__global__ __launch_bounds__(256) void kv_kernel()
{
    const int bh   = blockIdx.x;
    const int j0s  = blockIdx.y * 512;
    const int tid  = threadIdx.x;
    const int d    = tid & 31;
    const int gr   = tid >> 5;              // 0..7
    const int cbase = gr * 4;               // 0,4,..,28
    __shared__ float sk[64 * 32];
    __shared__ float sv[64 * 32];
    __shared__ float sred[256];
    const size_t base = (size_t)bh * NTOK * HD;
    float acc[4] = {0.f, 0.f, 0.f, 0.f};
    float ksacc = 0.f;

    for (int j0 = j0s; j0 < j0s + 512; j0 += 64) {
        for (int i = tid; i < 2048; i += 256) {
            sk[i] = g_k[base + (size_t)j0 * HD + i];
            sv[i] = g_v[base + (size_t)j0 * HD + i];
        }
        __syncthreads();
#pragma unroll 8
        for (int r = 0; r < 64; r++) {
            const float vv = sv[r * 32 + d];
#pragma unroll
            for (int q = 0; q < 4; q++) acc[q] += sk[r * 32 + cbase + q] * vv;
        }
#pragma unroll
        for (int r = 0; r < 8; r++) ksacc += sk[(gr + r * 8) * 32 + d];
        __syncthreads();
    }
#pragma unroll
    for (int q = 0; q < 4; q++)
        atomicAdd(&g_kv[bh * (HD * HD) + (cbase + q) * HD + d], acc[q]);

    sred[tid] = ksacc;
    __syncthreads();
    if (gr == 0) {
        float s = 0.f;
#pragma unroll
        for (int gg = 0; gg < 8; gg++) s += sred[gg * 32 + d];
        atomicAdd(&g_ksum[bh * HD + d], s);
    }
}

// ---------------------------------------------------------------------------
// Kernel 4: out = (q @ kv) * z + dwconv5x5(v) + dwc_b -> g_pre (B,N,C layout)
// ---------------------------------------------------------------------------
__global__ __launch_bounds__(256) void attn_out(const float* __restrict__ dwc_w,
                                                const float* __restrict__ dwc_b)
{
    const int bh = blockIdx.y;
    const int rowblk = blockIdx.x;
    const int tid = threadIdx.x;
    const int r = tid >> 5, d = tid & 31;
    const int n = rowblk * 8 + r;

    __shared__ float skv[HD * HD];
    __shared__ float sksum[HD];
    __shared__ float sw[HD * 25];
    __shared__ float sq[8][HD];

    for (int i = tid; i < HD * HD; i += 256) skv[i] = g_kv[bh * (HD * HD) + i];
    if (tid < HD) sksum[tid] = g_ksum[bh * HD + tid];
    for (int i = tid; i < HD * 25; i += 256) sw[i] = dwc_w[i];

    const size_t base = (size_t)bh * NTOK * HD;
    sq[r][d] = g_q[base + (size_t)n * HD + d];
    __syncthreads();

    float p = sq[r][d] * sksum[d];
#pragma unroll
    for (int off = 16; off; off >>= 1) p += __shfl_xor_sync(0xffffffffu, p, off);
    const float z = 1.f / (p + EPS);

    float o = 0.f;
#pragma unroll
    for (int c = 0; c < HD; c++) o += sq[r][c] * skv[c * HD + d];
    o *= z;

    const int y = n >> 6, x = n & 63;
    float cv = dwc_b[d];
#pragma unroll
    for (int ky = 0; ky < 5; ky++) {
        const int yy = y + ky - 2;
        if ((unsigned)yy >= 64u) continue;
#pragma unroll
        for (int kx = 0; kx < 5; kx++) {
            const int xx = x + kx - 2;
            if ((unsigned)xx >= 64u) continue;
            cv += sw[d * 25 + ky * 5 + kx] *
                  g_v[base + (size_t)(yy * 64 + xx) * HD + d];
        }
    }

    const int b = bh / HEADS, h = bh % HEADS;
    g_pre[((size_t)(b * NTOK + n)) * CDIM + h * HD + d] = o + cv;
}

// ---------------------------------------------------------------------------
// Kernel 5: proj GEMM (M=65536, Nout=384, K=384) + bias -> out, tf32 mma.
// Same structure as qkv_gemm.
// ---------------------------------------------------------------------------
__global__ __launch_bounds__(256) void proj_gemm(const float* __restrict__ W,
                                                 const float* __restrict__ bias,
                                                 float* __restrict__ out)
{
    __shared__ float As[16 * LDA];
    __shared__ float Bs[16 * LDB];

    const int tid  = threadIdx.x;
    const int mB   = blockIdx.y * 128;
    const int jB   = blockIdx.x * 64;
    const int lane = tid & 31;
    const int warp = tid >> 5;
    const int g    = lane >> 2;
    const int t    = lane & 3;
    const int wM   = (warp & 3) * 32;
    const int wN   = (warp >> 2) * 32;

    const int arow = tid >> 1;
    const int ak   = (tid & 1) * 8;
    const int brow = tid >> 2;
    const int bk   = (tid & 3) * 4;

    float acc[2][4][4];
#pragma unroll
    for (int i = 0; i < 2; i++)
#pragma unroll
        for (int j = 0; j < 4; j++)
#pragma unroll
            for (int l = 0; l < 4; l++) acc[i][j][l] = 0.f;

    for (int k0 = 0; k0 < CDIM; k0 += 16) {
        float4 av0 = *(const float4*)&g_pre[(size_t)(mB + arow) * CDIM + k0 + ak];
        float4 av1 = *(const float4*)&g_pre[(size_t)(mB + arow) * CDIM + k0 + ak + 4];
        float4 bv  = *(const float4*)&W[(size_t)(jB + brow) * CDIM + k0 + bk];

        As[(ak + 0) * LDA + arow] = f2tf(av0.x);
        As[(ak + 1) * LDA + arow] = f2tf(av0.y);
        As[(ak + 2) * LDA + arow] = f2tf(av0.z);
        As[(ak + 3) * LDA + arow] = f2tf(av0.w);
        As[(ak + 4) * LDA + arow] = f2tf(av1.x);
        As[(ak + 5) * LDA + arow] = f2tf(av1.y);
        As[(ak + 6) * LDA + arow] = f2tf(av1.z);
        As[(ak + 7) * LDA + arow] = f2tf(av1.w);
        Bs[(bk + 0) * LDB + brow] = f2tf(bv.x);
        Bs[(bk + 1) * LDB + brow] = f2tf(bv.y);
        Bs[(bk + 2) * LDB + brow] = f2tf(bv.z);
        Bs[(bk + 3) * LDB + brow] = f2tf(bv.w);
        __syncthreads();

#pragma unroll
        for (int ks = 0; ks < 16; ks += 8) {
            float a[2][4], b[4][2];
#pragma unroll
            for (int mt = 0; mt < 2; mt++) {
                const float* p0 = &As[(ks + t)     * LDA + wM + mt * 16 + g];
                const float* p1 = &As[(ks + t + 4) * LDA + wM + mt * 16 + g];
                a[mt][0] = p0[0]; a[mt][1] = p0[8];
                a[mt][2] = p1[0]; a[mt][3] = p1[8];
            }
#pragma unroll
            for (int nt = 0; nt < 4; nt++) {
                b[nt][0] = Bs[(ks + t)     * LDB + wN + nt * 8 + g];
                b[nt][1] = Bs[(ks + t + 4) * LDB + wN + nt * 8 + g];
            }
#pragma unroll
            for (int mt = 0; mt < 2; mt++)
#pragma unroll
                for (int nt = 0; nt < 4; nt++)
                    mma_tf32(acc[mt][nt], a[mt], b[nt]);
        }
        __syncthreads();
    }

#pragma unroll
    for (int mt = 0; mt < 2; mt++) {
#pragma unroll
        for (int nt = 0; nt < 4; nt++) {
            const int j = jB + wN + nt * 8 + 2 * t;
            const float b0 = bias[j], b1 = bias[j + 1];
#pragma unroll
            for (int hh = 0; hh < 2; hh++) {
                const int m = mB + wM + mt * 16 + g + hh * 8;
                *(float2*)&out[(size_t)m * CDIM + j] =
                    make_float2(acc[mt][nt][hh * 2 + 0] + b0,
                                acc[mt][nt][hh * 2 + 1] + b1);
            }
        }
    }
}

// ---------------------------------------------------------------------------
extern "C" void kernel_launch(void* const* d_in, const int* in_sizes, int n_in,
                              void* d_out, int out_size)
{
    const float* x      = (const float*)d_in[0];
    const float* qkv_w  = (const float*)d_in[1];
    const float* pos    = (const float*)d_in[2];
    const float* dwc_w  = (const float*)d_in[3];
    const float* dwc_b  = (const float*)d_in[4];
    const float* proj_w = (const float*)d_in[5];
    const float* proj_b = (const float*)d_in[6];
    float* out = (float*)d_out;

    dim3 g1(3 * CDIM / 64, M_TOT / 128);  // 18 x 512
    qkv_gemm<<<g1, 256>>>(x, qkv_w, pos);

    zero_kv<<<(BH_TOT * HD * HD + 255) / 256, 256>>>();

    dim3 g3(BH_TOT, 8);
    kv_kernel<<<g3, 256>>>();

    dim3 g4(NTOK / 8, BH_TOT);            // 512 x 192
    attn_out<<<g4, 256>>>(dwc_w, dwc_b);

    dim3 g5(CDIM / 64, M_TOT / 128);      // 6 x 512
    proj_gemm<<<g5, 256>>>(proj_w, proj_b, out);
}

// round 4
// speedup vs baseline: 2.9318x; 1.3923x over previous
#include <cuda_runtime.h>
#include <cuda_bf16.h>

// ---------------------------------------------------------------------------
// SlabAttention: B=16, N=4096, C=384, H=12, hd=32, BH=192
// Round 3: double-buffered cp.async tf32 GEMMs (BK=32), smem-tiled attn_out.
// ---------------------------------------------------------------------------

#define BATCH   16
#define NTOK    4096
#define CDIM    384
#define HEADS   12
#define HD      32
#define BH_TOT  (BATCH*HEADS)      // 192
#define M_TOT   (BATCH*NTOK)       // 65536
#define EPS     1e-6f

#define BK   32
#define LDK  36                     // row stride (floats): 32 + 4 pad -> 4g+t banks

// scratch (device globals; allocation-free rule)
__device__ float g_q  [(size_t)BH_TOT * NTOK * HD];
__device__ float g_k  [(size_t)BH_TOT * NTOK * HD];
__device__ float g_v  [(size_t)BH_TOT * NTOK * HD];
__device__ float g_pre[(size_t)M_TOT * CDIM];
__device__ float g_ksum[BH_TOT * HD];
__device__ float g_kv  [BH_TOT * HD * HD];

__device__ __forceinline__ float f2tf(float x) {
    asm("cvt.rna.tf32.f32 %0, %1;" : "=f"(x) : "f"(x));
    return x;
}

__device__ __forceinline__ void mma_tf32(float* c, const float* a, const float* b) {
    const unsigned* A = reinterpret_cast<const unsigned*>(a);
    const unsigned* B = reinterpret_cast<const unsigned*>(b);
    asm volatile(
        "mma.sync.aligned.m16n8k8.row.col.f32.tf32.tf32.f32 "
        "{%0,%1,%2,%3},{%4,%5,%6,%7},{%8,%9},{%0,%1,%2,%3};\n"
        : "+f"(c[0]), "+f"(c[1]), "+f"(c[2]), "+f"(c[3])
        : "r"(A[0]), "r"(A[1]), "r"(A[2]), "r"(A[3]), "r"(B[0]), "r"(B[1]));
}

__device__ __forceinline__ void cp16(float* smem, const float* g) {
    unsigned saddr = (unsigned)__cvta_generic_to_shared(smem);
    asm volatile("cp.async.ca.shared.global [%0], [%1], 16;\n" :: "r"(saddr), "l"(g));
}
#define CP_COMMIT  asm volatile("cp.async.commit_group;\n")
#define CP_WAIT(n) asm volatile("cp.async.wait_group %0;\n" :: "n"(n))

// smem bytes for gemm: 2 A stages (128*LDK) + 2 B stages (64*LDK)
#define GEMM_SMEM ((2*128*LDK + 2*64*LDK) * 4)

// ---------------------------------------------------------------------------
// Kernel 1: qkv GEMM (M=65536, Nout=1152, K=384), tf32 mma, 2-stage cp.async.
// BM=128, BN=64, BK=32, 256 threads (8 warps 4Mx2N), warp tile 32x32.
// ---------------------------------------------------------------------------
__global__ __launch_bounds__(256) void qkv_gemm(const float* __restrict__ A,
                                                const float* __restrict__ W,
                                                const float* __restrict__ pos)
{
    extern __shared__ float sm[];
    float* As[2] = { sm,               sm + 128 * LDK };
    float* Bs[2] = { sm + 2*128*LDK,   sm + 2*128*LDK + 64 * LDK };

    const int tid  = threadIdx.x;
    const int mB   = blockIdx.y * 128;
    const int jB   = blockIdx.x * 64;
    const int lane = tid & 31;
    const int warp = tid >> 5;
    const int g    = lane >> 2;
    const int t    = lane & 3;
    const int wM   = (warp & 3) * 32;
    const int wN   = (warp >> 2) * 32;

    const int am  = tid >> 3;          // 0..31
    const int akc = (tid & 7) * 4;     // 0,4,..,28

    float acc[2][4][4];
#pragma unroll
    for (int i = 0; i < 2; i++)
#pragma unroll
        for (int j = 0; j < 4; j++)
#pragma unroll
            for (int l = 0; l < 4; l++) acc[i][j][l] = 0.f;

#define LOAD_STAGE(s, k0)                                                         \
    {                                                                             \
        _Pragma("unroll")                                                         \
        for (int r = 0; r < 4; r++)                                               \
            cp16(&As[s][(am + r*32)*LDK + akc],                                   \
                 &A[(size_t)(mB + am + r*32)*CDIM + (k0) + akc]);                 \
        _Pragma("unroll")                                                         \
        for (int r = 0; r < 2; r++)                                               \
            cp16(&Bs[s][(am + r*32)*LDK + akc],                                   \
                 &W[(size_t)(jB + am + r*32)*CDIM + (k0) + akc]);                 \
        CP_COMMIT;                                                                \
    }

    LOAD_STAGE(0, 0);
    int s = 0;
    for (int k0 = 0; k0 < CDIM; k0 += BK) {
        if (k0 + BK < CDIM) { LOAD_STAGE(s ^ 1, k0 + BK); CP_WAIT(1); }
        else                { CP_WAIT(0); }
        __syncthreads();
        const float* as = As[s];
        const float* bs = Bs[s];
#pragma unroll
        for (int ks = 0; ks < BK; ks += 8) {
            float a[2][4], b[4][2];
#pragma unroll
            for (int mt = 0; mt < 2; mt++) {
                const int m0 = wM + mt * 16 + g;
                a[mt][0] = f2tf(as[ m0      * LDK + ks + t]);
                a[mt][1] = f2tf(as[(m0 + 8) * LDK + ks + t]);
                a[mt][2] = f2tf(as[ m0      * LDK + ks + t + 4]);
                a[mt][3] = f2tf(as[(m0 + 8) * LDK + ks + t + 4]);
            }
#pragma unroll
            for (int nt = 0; nt < 4; nt++) {
                const int n0 = wN + nt * 8 + g;
                b[nt][0] = f2tf(bs[n0 * LDK + ks + t]);
                b[nt][1] = f2tf(bs[n0 * LDK + ks + t + 4]);
            }
#pragma unroll
            for (int mt = 0; mt < 2; mt++)
#pragma unroll
                for (int nt = 0; nt < 4; nt++)
                    mma_tf32(acc[mt][nt], a[mt], b[nt]);
        }
        __syncthreads();
        s ^= 1;
    }
#undef LOAD_STAGE

    const int part = jB / CDIM;                 // 0=q, 1=k, 2=v (uniform/block)
#pragma unroll
    for (int mt = 0; mt < 2; mt++) {
#pragma unroll
        for (int nt = 0; nt < 4; nt++) {
            const int j = jB + wN + nt * 8 + 2 * t;
            const int c = j - part * CDIM;
            const int h = c >> 5;
            const int d = c & 31;
#pragma unroll
            for (int hh = 0; hh < 2; hh++) {
                const int m = mB + wM + mt * 16 + g + hh * 8;
                const int b_ = m >> 12;
                const int n  = m & 4095;
                float v0 = acc[mt][nt][hh * 2 + 0];
                float v1 = acc[mt][nt][hh * 2 + 1];
                const size_t o = (((size_t)(b_ * HEADS + h)) * NTOK + n) * HD + d;
                if (part == 0) {
                    *(float2*)&g_q[o] = make_float2(fmaxf(v0, 0.f), fmaxf(v1, 0.f));
                } else if (part == 1) {
                    v0 = fmaxf(v0 + pos[(size_t)n * CDIM + c],     0.f);
                    v1 = fmaxf(v1 + pos[(size_t)n * CDIM + c + 1], 0.f);
                    *(float2*)&g_k[o] = make_float2(v0, v1);
                } else {
                    *(float2*)&g_v[o] = make_float2(v0, v1);
                }
            }
        }
    }
}

// ---------------------------------------------------------------------------
__global__ __launch_bounds__(256) void zero_kv()
{
    const int i = blockIdx.x * 256 + threadIdx.x;
    if (i < BH_TOT * HD * HD) g_kv[i] = 0.f;
    if (i < BH_TOT * HD)      g_ksum[i] = 0.f;
}

// ---------------------------------------------------------------------------
// Kernel 2: kv[bh,c,d] += sum_{chunk} k*v ; ksum fused. grid (192, 8).
// ---------------------------------------------------------------------------
__global__ __launch_bounds__(256) void kv_kernel()
{
    const int bh   = blockIdx.x;
    const int j0s  = blockIdx.y * 512;
    const int tid  = threadIdx.x;
    const int d    = tid & 31;
    const int gr   = tid >> 5;
    const int cbase = gr * 4;
    __shared__ float sk[64 * 32];
    __shared__ float sv[64 * 32];
    __shared__ float sred[256];
    const size_t base = (size_t)bh * NTOK * HD;
    float acc[4] = {0.f, 0.f, 0.f, 0.f};
    float ksacc = 0.f;

    for (int j0 = j0s; j0 < j0s + 512; j0 += 64) {
        for (int i = tid; i < 2048; i += 256) {
            sk[i] = g_k[base + (size_t)j0 * HD + i];
            sv[i] = g_v[base + (size_t)j0 * HD + i];
        }
        __syncthreads();
#pragma unroll 8
        for (int r = 0; r < 64; r++) {
            const float vv = sv[r * 32 + d];
#pragma unroll
            for (int q = 0; q < 4; q++) acc[q] += sk[r * 32 + cbase + q] * vv;
        }
#pragma unroll
        for (int r = 0; r < 8; r++) ksacc += sk[(gr + r * 8) * 32 + d];
        __syncthreads();
    }
#pragma unroll
    for (int q = 0; q < 4; q++)
        atomicAdd(&g_kv[bh * (HD * HD) + (cbase + q) * HD + d], acc[q]);

    sred[tid] = ksacc;
    __syncthreads();
    if (gr == 0) {
        float ssum = 0.f;
#pragma unroll
        for (int gg = 0; gg < 8; gg++) ssum += sred[gg * 32 + d];
        atomicAdd(&g_ksum[bh * HD + d], ssum);
    }
}

// ---------------------------------------------------------------------------
// Kernel 4: attn_out v2. Block = one y-row (64 tokens x 32 ch) of one bh.
// Conv input (5 rows + x-halo) in smem; kv column + conv weights in regs.
// Each thread: fixed d, 8 consecutive x outputs, sliding window.
// grid (64, 192), 256 threads.
// ---------------------------------------------------------------------------
#define SV_ROW (68 * 32)
#define ATTN_SMEM ((5*SV_ROW + 2048 + 1024 + 800 + 32) * 4)

__global__ __launch_bounds__(256, 2) void attn_out(const float* __restrict__ dwc_w,
                                                   const float* __restrict__ dwc_b)
{
    extern __shared__ float sm[];
    float* sv  = sm;                    // 5 * 68 * 32
    float* sq  = sv + 5 * SV_ROW;       // 64 * 32
    float* skv = sq + 2048;             // 1024
    float* sw  = skv + 1024;            // 800
    float* sks = sw + 800;              // 32

    const int y  = blockIdx.x;
    const int bh = blockIdx.y;
    const int tid = threadIdx.x;
    const int d  = tid & 31;
    const int gr = tid >> 5;
    const int x0 = gr * 8;
    const size_t base = (size_t)bh * NTOK * HD;

    // zero x-halo columns (x = 0,1,66,67) of all 5 rows
    for (int i = tid; i < 5 * 4 * 32; i += 256) {
        const int row = i >> 7;
        const int rem = i & 127;
        const int col = rem >> 5;
        const int dd  = rem & 31;
        const int xc  = (col < 2) ? col : (64 + col);
        sv[row * SV_ROW + xc * 32 + dd] = 0.f;
    }
    // 5 input rows of v (zero OOB rows)
#pragma unroll
    for (int ky = 0; ky < 5; ky++) {
        const int yy = y + ky - 2;
        for (int c = tid; c < 512; c += 256) {
            const int x = c >> 3, dq = (c & 7) * 4;
            float4 val = make_float4(0.f, 0.f, 0.f, 0.f);
            if ((unsigned)yy < 64u)
                val = *(const float4*)&g_v[base + ((size_t)(yy * 64 + x)) * HD + dq];
            *(float4*)&sv[ky * SV_ROW + (x + 2) * 32 + dq] = val;
        }
    }
    // q row
    for (int c = tid; c < 512; c += 256) {
        const int x = c >> 3, dq = (c & 7) * 4;
        *(float4*)&sq[x * 32 + dq] =
            *(const float4*)&g_q[base + ((size_t)(y * 64 + x)) * HD + dq];
    }
    // kv, weights, ksum
    *(float4*)&skv[tid * 4] = *(const float4*)&g_kv[bh * 1024 + tid * 4];
    for (int i = tid; i < 800; i += 256) sw[i] = dwc_w[i];
    if (tid < 32) sks[tid] = g_ksum[bh * HD + tid];
    __syncthreads();

    float rkv[32];
#pragma unroll
    for (int c = 0; c < 32; c++) rkv[c] = skv[c * 32 + d];
    float rw[25];
#pragma unroll
    for (int k = 0; k < 25; k++) rw[k] = sw[d * 25 + k];
    const float rks = sks[d];
    const float rb  = dwc_b[d];

    // depthwise 5x5, 8 outputs per thread via sliding window
    float acc[8];
#pragma unroll
    for (int xi = 0; xi < 8; xi++) acc[xi] = rb;
#pragma unroll
    for (int ky = 0; ky < 5; ky++) {
        float w[12];
#pragma unroll
        for (int j = 0; j < 12; j++) w[j] = sv[ky * SV_ROW + (x0 + j) * 32 + d];
#pragma unroll
        for (int kx = 0; kx < 5; kx++) {
            const float cf = rw[ky * 5 + kx];
#pragma unroll
            for (int xi = 0; xi < 8; xi++) acc[xi] += cf * w[xi + kx];
        }
    }

    const int b_ = bh / HEADS, h = bh % HEADS;
#pragma unroll
    for (int xi = 0; xi < 8; xi++) {
        const int tok = x0 + xi;
        float o = 0.f;
#pragma unroll
        for (int c = 0; c < 32; c++) o += sq[tok * 32 + c] * rkv[c];
        float p = sq[tok * 32 + d] * rks;
#pragma unroll
        for (int off = 16; off; off >>= 1) p += __shfl_xor_sync(0xffffffffu, p, off);
        const float z = 1.f / (p + EPS);
        const int n = y * 64 + tok;
        g_pre[((size_t)(b_ * NTOK + n)) * CDIM + h * HD + d] = o * z + acc[xi];
    }
}

// ---------------------------------------------------------------------------
// Kernel 5: proj GEMM (M=65536, Nout=384, K=384) + bias, same pipeline.
// ---------------------------------------------------------------------------
__global__ __launch_bounds__(256) void proj_gemm(const float* __restrict__ W,
                                                 const float* __restrict__ bias,
                                                 float* __restrict__ out)
{
    extern __shared__ float sm[];
    float* As[2] = { sm,               sm + 128 * LDK };
    float* Bs[2] = { sm + 2*128*LDK,   sm + 2*128*LDK + 64 * LDK };

    const int tid  = threadIdx.x;
    const int mB   = blockIdx.y * 128;
    const int jB   = blockIdx.x * 64;
    const int lane = tid & 31;
    const int warp = tid >> 5;
    const int g    = lane >> 2;
    const int t    = lane & 3;
    const int wM   = (warp & 3) * 32;
    const int wN   = (warp >> 2) * 32;

    const int am  = tid >> 3;
    const int akc = (tid & 7) * 4;

    float acc[2][4][4];
#pragma unroll
    for (int i = 0; i < 2; i++)
#pragma unroll
        for (int j = 0; j < 4; j++)
#pragma unroll
            for (int l = 0; l < 4; l++) acc[i][j][l] = 0.f;

#define LOAD_STAGE(s, k0)                                                         \
    {                                                                             \
        _Pragma("unroll")                                                         \
        for (int r = 0; r < 4; r++)                                               \
            cp16(&As[s][(am + r*32)*LDK + akc],                                   \
                 &g_pre[(size_t)(mB + am + r*32)*CDIM + (k0) + akc]);             \
        _Pragma("unroll")                                                         \
        for (int r = 0; r < 2; r++)                                               \
            cp16(&Bs[s][(am + r*32)*LDK + akc],                                   \
                 &W[(size_t)(jB + am + r*32)*CDIM + (k0) + akc]);                 \
        CP_COMMIT;                                                                \
    }

    LOAD_STAGE(0, 0);
    int s = 0;
    for (int k0 = 0; k0 < CDIM; k0 += BK) {
        if (k0 + BK < CDIM) { LOAD_STAGE(s ^ 1, k0 + BK); CP_WAIT(1); }
        else                { CP_WAIT(0); }
        __syncthreads();
        const float* as = As[s];
        const float* bs = Bs[s];
#pragma unroll
        for (int ks = 0; ks < BK; ks += 8) {
            float a[2][4], b[4][2];
#pragma unroll
            for (int mt = 0; mt < 2; mt++) {
                const int m0 = wM + mt * 16 + g;
                a[mt][0] = f2tf(as[ m0      * LDK + ks + t]);
                a[mt][1] = f2tf(as[(m0 + 8) * LDK + ks + t]);
                a[mt][2] = f2tf(as[ m0      * LDK + ks + t + 4]);
                a[mt][3] = f2tf(as[(m0 + 8) * LDK + ks + t + 4]);
            }
#pragma unroll
            for (int nt = 0; nt < 4; nt++) {
                const int n0 = wN + nt * 8 + g;
                b[nt][0] = f2tf(bs[n0 * LDK + ks + t]);
                b[nt][1] = f2tf(bs[n0 * LDK + ks + t + 4]);
            }
#pragma unroll
            for (int mt = 0; mt < 2; mt++)
#pragma unroll
                for (int nt = 0; nt < 4; nt++)
                    mma_tf32(acc[mt][nt], a[mt], b[nt]);
        }
        __syncthreads();
        s ^= 1;
    }
#undef LOAD_STAGE

#pragma unroll
    for (int mt = 0; mt < 2; mt++) {
#pragma unroll
        for (int nt = 0; nt < 4; nt++) {
            const int j = jB + wN + nt * 8 + 2 * t;
            const float b0 = bias[j], b1 = bias[j + 1];
#pragma unroll
            for (int hh = 0; hh < 2; hh++) {
                const int m = mB + wM + mt * 16 + g + hh * 8;
                *(float2*)&out[(size_t)m * CDIM + j] =
                    make_float2(acc[mt][nt][hh * 2 + 0] + b0,
                                acc[mt][nt][hh * 2 + 1] + b1);
            }
        }
    }
}

// ---------------------------------------------------------------------------
extern "C" void kernel_launch(void* const* d_in, const int* in_sizes, int n_in,
                              void* d_out, int out_size)
{
    const float* x      = (const float*)d_in[0];
    const float* qkv_w  = (const float*)d_in[1];
    const float* pos    = (const float*)d_in[2];
    const float* dwc_w  = (const float*)d_in[3];
    const float* dwc_b  = (const float*)d_in[4];
    const float* proj_w = (const float*)d_in[5];
    const float* proj_b = (const float*)d_in[6];
    float* out = (float*)d_out;

    cudaFuncSetAttribute(qkv_gemm,  cudaFuncAttributeMaxDynamicSharedMemorySize, GEMM_SMEM);
    cudaFuncSetAttribute(proj_gemm, cudaFuncAttributeMaxDynamicSharedMemorySize, GEMM_SMEM);
    cudaFuncSetAttribute(attn_out,  cudaFuncAttributeMaxDynamicSharedMemorySize, ATTN_SMEM);

    dim3 g1(3 * CDIM / 64, M_TOT / 128);  // 18 x 512
    qkv_gemm<<<g1, 256, GEMM_SMEM>>>(x, qkv_w, pos);

    zero_kv<<<(BH_TOT * HD * HD + 255) / 256, 256>>>();

    dim3 g3(BH_TOT, 8);
    kv_kernel<<<g3, 256>>>();

    dim3 g4(64, BH_TOT);                  // y-rows x bh
    attn_out<<<g4, 256, ATTN_SMEM>>>(dwc_w, dwc_b);

    dim3 g5(CDIM / 64, M_TOT / 128);      // 3 x 512
    proj_gemm<<<g5, 256, GEMM_SMEM>>>(proj_w, proj_b, out);
}

// round 5
// speedup vs baseline: 3.5910x; 1.2248x over previous
#include <cuda_runtime.h>
#include <cuda_fp16.h>

// ---------------------------------------------------------------------------
// SlabAttention: B=16, N=4096, C=384, H=12, hd=32, BH=192
// Round 4: fp16-operand m16n8k16 mma GEMMs (fp32 accum), fp16 intermediates.
// ---------------------------------------------------------------------------

#define BATCH   16
#define NTOK    4096
#define CDIM    384
#define HEADS   12
#define HD      32
#define BH_TOT  (BATCH*HEADS)      // 192
#define M_TOT   (BATCH*NTOK)       // 65536
#define EPS     1e-6f

#define BK   32
#define LDH  40    // halfs per smem row: 32 + 8 pad (80B stride, conflict-free)

// scratch (device globals; allocation-free rule)
__device__ __half g_xh   [(size_t)M_TOT * CDIM];
__device__ __half g_wqkv [(size_t)3 * CDIM * CDIM];
__device__ __half g_wproj[(size_t)CDIM * CDIM];
__device__ __half g_qh   [(size_t)BH_TOT * NTOK * HD];
__device__ __half g_kh   [(size_t)BH_TOT * NTOK * HD];
__device__ __half g_vh   [(size_t)BH_TOT * NTOK * HD];
__device__ __half g_preh [(size_t)M_TOT * CDIM];
__device__ float  g_ksum [BH_TOT * HD];
__device__ float  g_kv   [BH_TOT * HD * HD];

__device__ __forceinline__ void mma_f16(float* c, const unsigned* A, const unsigned* B) {
    asm volatile(
        "mma.sync.aligned.m16n8k16.row.col.f32.f16.f16.f32 "
        "{%0,%1,%2,%3},{%4,%5,%6,%7},{%8,%9},{%0,%1,%2,%3};\n"
        : "+f"(c[0]), "+f"(c[1]), "+f"(c[2]), "+f"(c[3])
        : "r"(A[0]), "r"(A[1]), "r"(A[2]), "r"(A[3]), "r"(B[0]), "r"(B[1]));
}

__device__ __forceinline__ void cp8(__half* smem, const __half* g) {
    unsigned saddr = (unsigned)__cvta_generic_to_shared(smem);
    asm volatile("cp.async.ca.shared.global [%0], [%1], 8;\n" :: "r"(saddr), "l"(g));
}
#define CP_COMMIT  asm volatile("cp.async.commit_group;\n")
#define CP_WAIT(n) asm volatile("cp.async.wait_group %0;\n" :: "n"(n))

// smem: 2 stages x (A 128 rows + B 128 rows) x LDH halfs
#define GEMM_SMEM (4 * 128 * LDH * 2)

// ---------------------------------------------------------------------------
// Conversion kernels
// ---------------------------------------------------------------------------
__global__ __launch_bounds__(256) void cvt_x(const float4* __restrict__ x)
{
    const size_t i = (size_t)blockIdx.x * 256 + threadIdx.x;   // < 6291456
    float4 v = x[i];
    *(__half2*)&g_xh[i * 4]     = __floats2half2_rn(v.x, v.y);
    *(__half2*)&g_xh[i * 4 + 2] = __floats2half2_rn(v.z, v.w);
}

__global__ __launch_bounds__(256) void cvt_w(const float* __restrict__ qkv_w,
                                             const float* __restrict__ proj_w)
{
    const int i = blockIdx.x * 256 + threadIdx.x;              // < 589824
    if (i < 3 * CDIM * CDIM) g_wqkv[i] = __float2half_rn(qkv_w[i]);
    else g_wproj[i - 3 * CDIM * CDIM] = __float2half_rn(proj_w[i - 3 * CDIM * CDIM]);
}

// ---------------------------------------------------------------------------
// Kernel 1: qkv GEMM (M=65536, Nout=1152, K=384), fp16 mma, 2-stage cp.async.
// BM=128, BN=128, BK=32, 256 threads (8 warps 2Mx4N), warp tile 64x32.
// ---------------------------------------------------------------------------
__global__ __launch_bounds__(256) void qkv_gemm(const float* __restrict__ pos)
{
    extern __shared__ __half smh[];
    __half* As[2] = { smh,               smh + 128 * LDH };
    __half* Bs[2] = { smh + 2*128*LDH,   smh + 3*128*LDH };

    const int tid  = threadIdx.x;
    const int mB   = blockIdx.y * 128;
    const int jB   = blockIdx.x * 128;
    const int lane = tid & 31;
    const int warp = tid >> 5;
    const int g    = lane >> 2;
    const int t    = lane & 3;
    const int wM   = (warp & 1) * 64;
    const int wN   = (warp >> 1) * 32;

    const int lrow = tid >> 1;          // 0..127
    const int lseg = (tid & 1) * 16;    // half offset 0 or 16

    float acc[4][4][4];
#pragma unroll
    for (int i = 0; i < 4; i++)
#pragma unroll
        for (int j = 0; j < 4; j++)
#pragma unroll
            for (int l = 0; l < 4; l++) acc[i][j][l] = 0.f;

#define LOAD_STAGE(s, k0)                                                       \
    {                                                                           \
        _Pragma("unroll")                                                       \
        for (int i = 0; i < 4; i++) {                                           \
            cp8(&As[s][lrow * LDH + lseg + i * 4],                              \
                &g_xh[(size_t)(mB + lrow) * CDIM + (k0) + lseg + i * 4]);       \
            cp8(&Bs[s][lrow * LDH + lseg + i * 4],                              \
                &g_wqkv[(size_t)(jB + lrow) * CDIM + (k0) + lseg + i * 4]);     \
        }                                                                       \
        CP_COMMIT;                                                              \
    }

    LOAD_STAGE(0, 0);
    int s = 0;
    for (int k0 = 0; k0 < CDIM; k0 += BK) {
        if (k0 + BK < CDIM) { LOAD_STAGE(s ^ 1, k0 + BK); CP_WAIT(1); }
        else                { CP_WAIT(0); }
        __syncthreads();
        const __half* as = As[s];
        const __half* bs = Bs[s];
#pragma unroll
        for (int ks = 0; ks < BK; ks += 16) {
            unsigned a[4][4], b[4][2];
#pragma unroll
            for (int mt = 0; mt < 4; mt++) {
                const int m0 = wM + mt * 16 + g;
                a[mt][0] = *(const unsigned*)&as[ m0      * LDH + ks + 2 * t];
                a[mt][1] = *(const unsigned*)&as[(m0 + 8) * LDH + ks + 2 * t];
                a[mt][2] = *(const unsigned*)&as[ m0      * LDH + ks + 2 * t + 8];
                a[mt][3] = *(const unsigned*)&as[(m0 + 8) * LDH + ks + 2 * t + 8];
            }
#pragma unroll
            for (int nt = 0; nt < 4; nt++) {
                const int n0 = wN + nt * 8 + g;
                b[nt][0] = *(const unsigned*)&bs[n0 * LDH + ks + 2 * t];
                b[nt][1] = *(const unsigned*)&bs[n0 * LDH + ks + 2 * t + 8];
            }
#pragma unroll
            for (int mt = 0; mt < 4; mt++)
#pragma unroll
                for (int nt = 0; nt < 4; nt++)
                    mma_f16(acc[mt][nt], a[mt], b[nt]);
        }
        __syncthreads();
        s ^= 1;
    }
#undef LOAD_STAGE

    // epilogue: 1152 = 9 blocks of 128; 384 = 3*128 -> part uniform per block
    const int part = jB / CDIM;                 // 0=q, 1=k, 2=v
#pragma unroll
    for (int mt = 0; mt < 4; mt++) {
#pragma unroll
        for (int nt = 0; nt < 4; nt++) {
            const int j = jB + wN + nt * 8 + 2 * t;
            const int c = j - part * CDIM;
            const int h = c >> 5;
            const int d = c & 31;
#pragma unroll
            for (int hh = 0; hh < 2; hh++) {
                const int m = mB + wM + mt * 16 + g + hh * 8;
                const int b_ = m >> 12;
                const int n  = m & 4095;
                float v0 = acc[mt][nt][hh * 2 + 0];
                float v1 = acc[mt][nt][hh * 2 + 1];
                const size_t o = (((size_t)(b_ * HEADS + h)) * NTOK + n) * HD + d;
                if (part == 0) {
                    *(__half2*)&g_qh[o] =
                        __floats2half2_rn(fmaxf(v0, 0.f), fmaxf(v1, 0.f));
                } else if (part == 1) {
                    v0 = fmaxf(v0 + pos[(size_t)n * CDIM + c],     0.f);
                    v1 = fmaxf(v1 + pos[(size_t)n * CDIM + c + 1], 0.f);
                    *(__half2*)&g_kh[o] = __floats2half2_rn(v0, v1);
                } else {
                    *(__half2*)&g_vh[o] = __floats2half2_rn(v0, v1);
                }
            }
        }
    }
}

// ---------------------------------------------------------------------------
__global__ __launch_bounds__(256) void zero_kv()
{
    const int i = blockIdx.x * 256 + threadIdx.x;
    if (i < BH_TOT * HD * HD) g_kv[i] = 0.f;
    if (i < BH_TOT * HD)      g_ksum[i] = 0.f;
}

// ---------------------------------------------------------------------------
// Kernel 2: kv[bh,c,d] += sum_{chunk} k*v ; ksum fused. grid (192, 8).
// ---------------------------------------------------------------------------
__global__ __launch_bounds__(256) void kv_kernel()
{
    const int bh   = blockIdx.x;
    const int j0s  = blockIdx.y * 512;
    const int tid  = threadIdx.x;
    const int d    = tid & 31;
    const int gr   = tid >> 5;
    const int cbase = gr * 4;
    __shared__ float sk[64 * 32];
    __shared__ float sv[64 * 32];
    __shared__ float sred[256];
    const size_t base = (size_t)bh * NTOK * HD;
    float acc[4] = {0.f, 0.f, 0.f, 0.f};
    float ksacc = 0.f;

    for (int j0 = j0s; j0 < j0s + 512; j0 += 64) {
        for (int i = tid; i < 512; i += 256) {
            const size_t gi = base + (size_t)j0 * HD + i * 4;
            float2 k01 = __half22float2(*(const __half2*)&g_kh[gi]);
            float2 k23 = __half22float2(*(const __half2*)&g_kh[gi + 2]);
            float2 v01 = __half22float2(*(const __half2*)&g_vh[gi]);
            float2 v23 = __half22float2(*(const __half2*)&g_vh[gi + 2]);
            *(float4*)&sk[i * 4] = make_float4(k01.x, k01.y, k23.x, k23.y);
            *(float4*)&sv[i * 4] = make_float4(v01.x, v01.y, v23.x, v23.y);
        }
        __syncthreads();
#pragma unroll 8
        for (int r = 0; r < 64; r++) {
            const float vv = sv[r * 32 + d];
#pragma unroll
            for (int q = 0; q < 4; q++) acc[q] += sk[r * 32 + cbase + q] * vv;
        }
#pragma unroll
        for (int r = 0; r < 8; r++) ksacc += sk[(gr + r * 8) * 32 + d];
        __syncthreads();
    }
#pragma unroll
    for (int q = 0; q < 4; q++)
        atomicAdd(&g_kv[bh * (HD * HD) + (cbase + q) * HD + d], acc[q]);

    sred[tid] = ksacc;
    __syncthreads();
    if (gr == 0) {
        float ssum = 0.f;
#pragma unroll
        for (int gg = 0; gg < 8; gg++) ssum += sred[gg * 32 + d];
        atomicAdd(&g_ksum[bh * HD + d], ssum);
    }
}

// ---------------------------------------------------------------------------
// Kernel 4: attn_out. Block = one y-row (64 tokens x 32 ch) of one bh.
// ---------------------------------------------------------------------------
#define SV_ROW (68 * 32)
#define ATTN_SMEM ((5*SV_ROW + 2048 + 1024 + 800 + 32) * 4)

__global__ __launch_bounds__(256, 2) void attn_out(const float* __restrict__ dwc_w,
                                                   const float* __restrict__ dwc_b)
{
    extern __shared__ float sm[];
    float* sv  = sm;                    // 5 * 68 * 32
    float* sq  = sv + 5 * SV_ROW;       // 64 * 32
    float* skv = sq + 2048;             // 1024
    float* sw  = skv + 1024;            // 800
    float* sks = sw + 800;              // 32

    const int y  = blockIdx.x;
    const int bh = blockIdx.y;
    const int tid = threadIdx.x;
    const int d  = tid & 31;
    const int gr = tid >> 5;
    const int x0 = gr * 8;
    const size_t base = (size_t)bh * NTOK * HD;

    // zero x-halo columns (x = 0,1,66,67) of all 5 rows
    for (int i = tid; i < 5 * 4 * 32; i += 256) {
        const int row = i >> 7;
        const int rem = i & 127;
        const int col = rem >> 5;
        const int dd  = rem & 31;
        const int xc  = (col < 2) ? col : (64 + col);
        sv[row * SV_ROW + xc * 32 + dd] = 0.f;
    }
    // 5 input rows of v (zero OOB rows)
#pragma unroll
    for (int ky = 0; ky < 5; ky++) {
        const int yy = y + ky - 2;
        for (int c = tid; c < 512; c += 256) {
            const int x = c >> 3, dq = (c & 7) * 4;
            float4 val = make_float4(0.f, 0.f, 0.f, 0.f);
            if ((unsigned)yy < 64u) {
                const size_t gi = base + ((size_t)(yy * 64 + x)) * HD + dq;
                float2 a = __half22float2(*(const __half2*)&g_vh[gi]);
                float2 bq = __half22float2(*(const __half2*)&g_vh[gi + 2]);
                val = make_float4(a.x, a.y, bq.x, bq.y);
            }
            *(float4*)&sv[ky * SV_ROW + (x + 2) * 32 + dq] = val;
        }
    }
    // q row
    for (int c = tid; c < 512; c += 256) {
        const int x = c >> 3, dq = (c & 7) * 4;
        const size_t gi = base + ((size_t)(y * 64 + x)) * HD + dq;
        float2 a = __half22float2(*(const __half2*)&g_qh[gi]);
        float2 bq = __half22float2(*(const __half2*)&g_qh[gi + 2]);
        *(float4*)&sq[x * 32 + dq] = make_float4(a.x, a.y, bq.x, bq.y);
    }
    // kv, weights, ksum
    *(float4*)&skv[tid * 4] = *(const float4*)&g_kv[bh * 1024 + tid * 4];
    for (int i = tid; i < 800; i += 256) sw[i] = dwc_w[i];
    if (tid < 32) sks[tid] = g_ksum[bh * HD + tid];
    __syncthreads();

    float rkv[32];
#pragma unroll
    for (int c = 0; c < 32; c++) rkv[c] = skv[c * 32 + d];
    float rw[25];
#pragma unroll
    for (int k = 0; k < 25; k++) rw[k] = sw[d * 25 + k];
    const float rks = sks[d];
    const float rb  = dwc_b[d];

    float acc[8];
#pragma unroll
    for (int xi = 0; xi < 8; xi++) acc[xi] = rb;
#pragma unroll
    for (int ky = 0; ky < 5; ky++) {
        float w[12];
#pragma unroll
        for (int j = 0; j < 12; j++) w[j] = sv[ky * SV_ROW + (x0 + j) * 32 + d];
#pragma unroll
        for (int kx = 0; kx < 5; kx++) {
            const float cf = rw[ky * 5 + kx];
#pragma unroll
            for (int xi = 0; xi < 8; xi++) acc[xi] += cf * w[xi + kx];
        }
    }

    const int b_ = bh / HEADS, h = bh % HEADS;
#pragma unroll
    for (int xi = 0; xi < 8; xi++) {
        const int tok = x0 + xi;
        float o = 0.f;
#pragma unroll
        for (int c = 0; c < 32; c++) o += sq[tok * 32 + c] * rkv[c];
        float p = sq[tok * 32 + d] * rks;
#pragma unroll
        for (int off = 16; off; off >>= 1) p += __shfl_xor_sync(0xffffffffu, p, off);
        const float z = 1.f / (p + EPS);
        const int n = y * 64 + tok;
        g_preh[((size_t)(b_ * NTOK + n)) * CDIM + h * HD + d] =
            __float2half_rn(o * z + acc[xi]);
    }
}

// ---------------------------------------------------------------------------
// Kernel 5: proj GEMM (M=65536, Nout=384, K=384) + bias -> out (fp32).
// ---------------------------------------------------------------------------
__global__ __launch_bounds__(256) void proj_gemm(const float* __restrict__ bias,
                                                 float* __restrict__ out)
{
    extern __shared__ __half smh[];
    __half* As[2] = { smh,               smh + 128 * LDH };
    __half* Bs[2] = { smh + 2*128*LDH,   smh + 3*128*LDH };

    const int tid  = threadIdx.x;
    const int mB   = blockIdx.y * 128;
    const int jB   = blockIdx.x * 128;
    const int lane = tid & 31;
    const int warp = tid >> 5;
    const int g    = lane >> 2;
    const int t    = lane & 3;
    const int wM   = (warp & 1) * 64;
    const int wN   = (warp >> 1) * 32;

    const int lrow = tid >> 1;
    const int lseg = (tid & 1) * 16;

    float acc[4][4][4];
#pragma unroll
    for (int i = 0; i < 4; i++)
#pragma unroll
        for (int j = 0; j < 4; j++)
#pragma unroll
            for (int l = 0; l < 4; l++) acc[i][j][l] = 0.f;

#define LOAD_STAGE(s, k0)                                                       \
    {                                                                           \
        _Pragma("unroll")                                                       \
        for (int i = 0; i < 4; i++) {                                           \
            cp8(&As[s][lrow * LDH + lseg + i * 4],                              \
                &g_preh[(size_t)(mB + lrow) * CDIM + (k0) + lseg + i * 4]);     \
            cp8(&Bs[s][lrow * LDH + lseg + i * 4],                              \
                &g_wproj[(size_t)(jB + lrow) * CDIM + (k0) + lseg + i * 4]);    \
        }                                                                       \
        CP_COMMIT;                                                              \
    }

    LOAD_STAGE(0, 0);
    int s = 0;
    for (int k0 = 0; k0 < CDIM; k0 += BK) {
        if (k0 + BK < CDIM) { LOAD_STAGE(s ^ 1, k0 + BK); CP_WAIT(1); }
        else                { CP_WAIT(0); }
        __syncthreads();
        const __half* as = As[s];
        const __half* bs = Bs[s];
#pragma unroll
        for (int ks = 0; ks < BK; ks += 16) {
            unsigned a[4][4], b[4][2];
#pragma unroll
            for (int mt = 0; mt < 4; mt++) {
                const int m0 = wM + mt * 16 + g;
                a[mt][0] = *(const unsigned*)&as[ m0      * LDH + ks + 2 * t];
                a[mt][1] = *(const unsigned*)&as[(m0 + 8) * LDH + ks + 2 * t];
                a[mt][2] = *(const unsigned*)&as[ m0      * LDH + ks + 2 * t + 8];
                a[mt][3] = *(const unsigned*)&as[(m0 + 8) * LDH + ks + 2 * t + 8];
            }
#pragma unroll
            for (int nt = 0; nt < 4; nt++) {
                const int n0 = wN + nt * 8 + g;
                b[nt][0] = *(const unsigned*)&bs[n0 * LDH + ks + 2 * t];
                b[nt][1] = *(const unsigned*)&bs[n0 * LDH + ks + 2 * t + 8];
            }
#pragma unroll
            for (int mt = 0; mt < 4; mt++)
#pragma unroll
                for (int nt = 0; nt < 4; nt++)
                    mma_f16(acc[mt][nt], a[mt], b[nt]);
        }
        __syncthreads();
        s ^= 1;
    }
#undef LOAD_STAGE

#pragma unroll
    for (int mt = 0; mt < 4; mt++) {
#pragma unroll
        for (int nt = 0; nt < 4; nt++) {
            const int j = jB + wN + nt * 8 + 2 * t;
            const float b0 = bias[j], b1 = bias[j + 1];
#pragma unroll
            for (int hh = 0; hh < 2; hh++) {
                const int m = mB + wM + mt * 16 + g + hh * 8;
                *(float2*)&out[(size_t)m * CDIM + j] =
                    make_float2(acc[mt][nt][hh * 2 + 0] + b0,
                                acc[mt][nt][hh * 2 + 1] + b1);
            }
        }
    }
}

// ---------------------------------------------------------------------------
extern "C" void kernel_launch(void* const* d_in, const int* in_sizes, int n_in,
                              void* d_out, int out_size)
{
    const float* x      = (const float*)d_in[0];
    const float* qkv_w  = (const float*)d_in[1];
    const float* pos    = (const float*)d_in[2];
    const float* dwc_w  = (const float*)d_in[3];
    const float* dwc_b  = (const float*)d_in[4];
    const float* proj_w = (const float*)d_in[5];
    const float* proj_b = (const float*)d_in[6];
    float* out = (float*)d_out;

    cudaFuncSetAttribute(attn_out, cudaFuncAttributeMaxDynamicSharedMemorySize, ATTN_SMEM);

    cvt_x<<<24576, 256>>>((const float4*)x);
    cvt_w<<<2304, 256>>>(qkv_w, proj_w);

    dim3 g1(9, M_TOT / 128);              // 1152/128 x 512
    qkv_gemm<<<g1, 256, GEMM_SMEM>>>(pos);

    zero_kv<<<(BH_TOT * HD * HD + 255) / 256, 256>>>();

    dim3 g3(BH_TOT, 8);
    kv_kernel<<<g3, 256>>>();

    dim3 g4(64, BH_TOT);
    attn_out<<<g4, 256, ATTN_SMEM>>>(dwc_w, dwc_b);

    dim3 g5(3, M_TOT / 128);              // 384/128 x 512
    proj_gemm<<<g5, 256, GEMM_SMEM>>>(proj_b, out);
}

// round 6
// speedup vs baseline: 5.3089x; 1.4784x over previous
#include <cuda_runtime.h>
#include <cuda_fp16.h>

// ---------------------------------------------------------------------------
// SlabAttention: B=16, N=4096, C=384, H=12, hd=32, BH=192
// Round 5: ldmatrix fragment loads + cp.async.16B in GEMMs; attn_out occupancy
// (v-tile in fp16 smem, conv weights from smem, launch_bounds(256,4)).
// ---------------------------------------------------------------------------

#define BATCH   16
#define NTOK    4096
#define CDIM    384
#define HEADS   12
#define HD      32
#define BH_TOT  (BATCH*HEADS)      // 192
#define M_TOT   (BATCH*NTOK)       // 65536
#define EPS     1e-6f

#define BK   32
#define LDH  40    // halfs per smem row: 32 + 8 pad (80B stride)
                   // ldmatrix phase: chunk = (row*5 + col/8) mod 8, 5 coprime 8
                   // -> 8 consecutive rows hit 8 distinct 16B columns: conflict-free

// scratch (device globals; allocation-free rule)
__device__ alignas(256) __half g_xh   [(size_t)M_TOT * CDIM];
__device__ alignas(256) __half g_wqkv [(size_t)3 * CDIM * CDIM];
__device__ alignas(256) __half g_wproj[(size_t)CDIM * CDIM];
__device__ alignas(256) __half g_qh   [(size_t)BH_TOT * NTOK * HD];
__device__ alignas(256) __half g_kh   [(size_t)BH_TOT * NTOK * HD];
__device__ alignas(256) __half g_vh   [(size_t)BH_TOT * NTOK * HD];
__device__ alignas(256) __half g_preh [(size_t)M_TOT * CDIM];
__device__ float  g_ksum [BH_TOT * HD];
__device__ float  g_kv   [BH_TOT * HD * HD];

__device__ __forceinline__ void mma_f16(float* c, const unsigned* A, const unsigned* B) {
    asm volatile(
        "mma.sync.aligned.m16n8k16.row.col.f32.f16.f16.f32 "
        "{%0,%1,%2,%3},{%4,%5,%6,%7},{%8,%9},{%0,%1,%2,%3};\n"
        : "+f"(c[0]), "+f"(c[1]), "+f"(c[2]), "+f"(c[3])
        : "r"(A[0]), "r"(A[1]), "r"(A[2]), "r"(A[3]), "r"(B[0]), "r"(B[1]));
}

__device__ __forceinline__ void ldsm_x4(unsigned* r, unsigned addr) {
    asm volatile("ldmatrix.sync.aligned.m8n8.x4.shared.b16 {%0,%1,%2,%3}, [%4];\n"
        : "=r"(r[0]), "=r"(r[1]), "=r"(r[2]), "=r"(r[3]) : "r"(addr));
}

__device__ __forceinline__ void cp16h(__half* smem, const __half* g) {
    unsigned saddr = (unsigned)__cvta_generic_to_shared(smem);
    asm volatile("cp.async.cg.shared.global [%0], [%1], 16;\n" :: "r"(saddr), "l"(g));
}
#define CP_COMMIT  asm volatile("cp.async.commit_group;\n")
#define CP_WAIT(n) asm volatile("cp.async.wait_group %0;\n" :: "n"(n))

// smem: 2 stages x (A 128 rows + B 128 rows) x LDH halfs
#define GEMM_SMEM (4 * 128 * LDH * 2)

// ---------------------------------------------------------------------------
// Conversion kernels
// ---------------------------------------------------------------------------
__global__ __launch_bounds__(256) void cvt_x(const float4* __restrict__ x)
{
    const size_t i = (size_t)blockIdx.x * 256 + threadIdx.x;
    float4 v = x[i];
    *(__half2*)&g_xh[i * 4]     = __floats2half2_rn(v.x, v.y);
    *(__half2*)&g_xh[i * 4 + 2] = __floats2half2_rn(v.z, v.w);
}

__global__ __launch_bounds__(256) void cvt_w(const float* __restrict__ qkv_w,
                                             const float* __restrict__ proj_w)
{
    const int i = blockIdx.x * 256 + threadIdx.x;
    if (i < 3 * CDIM * CDIM) g_wqkv[i] = __float2half_rn(qkv_w[i]);
    else g_wproj[i - 3 * CDIM * CDIM] = __float2half_rn(proj_w[i - 3 * CDIM * CDIM]);
}

// ---------------------------------------------------------------------------
// GEMM core shared by qkv/proj: BM=128, BN=128, BK=32, 256 thr, warp 64x32.
// ---------------------------------------------------------------------------
#define GEMM_PROLOGUE(GA, GB)                                                   \
    extern __shared__ __half smh[];                                             \
    __half* As[2] = { smh,             smh + 128 * LDH };                       \
    __half* Bs[2] = { smh + 2*128*LDH, smh + 3*128*LDH };                       \
    const int tid  = threadIdx.x;                                               \
    const int mB   = blockIdx.y * 128;                                          \
    const int jB   = blockIdx.x * 128;                                          \
    const int lane = tid & 31;                                                  \
    const int warp = tid >> 5;                                                  \
    const int g    = lane >> 2;                                                 \
    const int t    = lane & 3;                                                  \
    const int wM   = (warp & 1) * 64;                                           \
    const int wN   = (warp >> 1) * 32;                                          \
    const int li   = lane & 7;                                                  \
    const int seg  = lane >> 3;                                                 \
    int aoff[4], boff[2];                                                       \
    _Pragma("unroll")                                                           \
    for (int mt = 0; mt < 4; mt++)                                              \
        aoff[mt] = (wM + mt*16 + li + (seg & 1)*8) * LDH + (seg >> 1)*8;        \
    _Pragma("unroll")                                                           \
    for (int np = 0; np < 2; np++)                                              \
        boff[np] = (wN + np*16 + li + (seg >> 1)*8) * LDH + (seg & 1)*8;        \
    float acc[4][4][4];                                                         \
    _Pragma("unroll")                                                           \
    for (int i = 0; i < 4; i++)                                                 \
        _Pragma("unroll")                                                       \
        for (int j = 0; j < 4; j++)                                             \
            _Pragma("unroll")                                                   \
            for (int l = 0; l < 4; l++) acc[i][j][l] = 0.f;

#define LOAD_STAGE(s, k0, GA, GB)                                               \
    {                                                                           \
        const int c0 = tid, c1 = tid + 256;                                     \
        cp16h(&As[s][(c0>>2)*LDH + (c0&3)*8],                                   \
              &GA[(size_t)(mB + (c0>>2))*CDIM + (k0) + (c0&3)*8]);              \
        cp16h(&Bs[s][(c0>>2)*LDH + (c0&3)*8],                                   \
              &GB[(size_t)(jB + (c0>>2))*CDIM + (k0) + (c0&3)*8]);              \
        cp16h(&As[s][(c1>>2)*LDH + (c1&3)*8],                                   \
              &GA[(size_t)(mB + (c1>>2))*CDIM + (k0) + (c1&3)*8]);              \
        cp16h(&Bs[s][(c1>>2)*LDH + (c1&3)*8],                                   \
              &GB[(size_t)(jB + (c1>>2))*CDIM + (k0) + (c1&3)*8]);              \
        CP_COMMIT;                                                              \
    }

#define GEMM_MAINLOOP(GA, GB)                                                   \
    LOAD_STAGE(0, 0, GA, GB);                                                   \
    int s = 0;                                                                  \
    for (int k0 = 0; k0 < CDIM; k0 += BK) {                                     \
        if (k0 + BK < CDIM) { LOAD_STAGE(s ^ 1, k0 + BK, GA, GB); CP_WAIT(1); } \
        else                { CP_WAIT(0); }                                     \
        __syncthreads();                                                        \
        const unsigned uA = (unsigned)__cvta_generic_to_shared(As[s]);          \
        const unsigned uB = (unsigned)__cvta_generic_to_shared(Bs[s]);          \
        _Pragma("unroll")                                                       \
        for (int ks = 0; ks < BK; ks += 16) {                                   \
            unsigned a[4][4], bb[2][4];                                         \
            _Pragma("unroll")                                                   \
            for (int mt = 0; mt < 4; mt++)                                      \
                ldsm_x4(a[mt], uA + 2u * (unsigned)(aoff[mt] + ks));            \
            _Pragma("unroll")                                                   \
            for (int np = 0; np < 2; np++)                                      \
                ldsm_x4(bb[np], uB + 2u * (unsigned)(boff[np] + ks));           \
            _Pragma("unroll")                                                   \
            for (int mt = 0; mt < 4; mt++)                                      \
                _Pragma("unroll")                                               \
                for (int nt = 0; nt < 4; nt++)                                  \
                    mma_f16(acc[mt][nt], a[mt], &bb[nt >> 1][(nt & 1) * 2]);    \
        }                                                                       \
        __syncthreads();                                                        \
        s ^= 1;                                                                 \
    }

// ---------------------------------------------------------------------------
// Kernel 1: qkv GEMM (M=65536, Nout=1152, K=384) + fused epilogue.
// ---------------------------------------------------------------------------
__global__ __launch_bounds__(256) void qkv_gemm(const float* __restrict__ pos)
{
    GEMM_PROLOGUE(g_xh, g_wqkv)
    GEMM_MAINLOOP(g_xh, g_wqkv)

    const int part = jB / CDIM;                 // 0=q, 1=k, 2=v (uniform/block)
#pragma unroll
    for (int mt = 0; mt < 4; mt++) {
#pragma unroll
        for (int nt = 0; nt < 4; nt++) {
            const int j = jB + wN + nt * 8 + 2 * t;
            const int c = j - part * CDIM;
            const int h = c >> 5;
            const int d = c & 31;
#pragma unroll
            for (int hh = 0; hh < 2; hh++) {
                const int m = mB + wM + mt * 16 + g + hh * 8;
                const int b_ = m >> 12;
                const int n  = m & 4095;
                float v0 = acc[mt][nt][hh * 2 + 0];
                float v1 = acc[mt][nt][hh * 2 + 1];
                const size_t o = (((size_t)(b_ * HEADS + h)) * NTOK + n) * HD + d;
                if (part == 0) {
                    *(__half2*)&g_qh[o] =
                        __floats2half2_rn(fmaxf(v0, 0.f), fmaxf(v1, 0.f));
                } else if (part == 1) {
                    v0 = fmaxf(v0 + pos[(size_t)n * CDIM + c],     0.f);
                    v1 = fmaxf(v1 + pos[(size_t)n * CDIM + c + 1], 0.f);
                    *(__half2*)&g_kh[o] = __floats2half2_rn(v0, v1);
                } else {
                    *(__half2*)&g_vh[o] = __floats2half2_rn(v0, v1);
                }
            }
        }
    }
}

// ---------------------------------------------------------------------------
__global__ __launch_bounds__(256) void zero_kv()
{
    const int i = blockIdx.x * 256 + threadIdx.x;
    if (i < BH_TOT * HD * HD) g_kv[i] = 0.f;
    if (i < BH_TOT * HD)      g_ksum[i] = 0.f;
}

// ---------------------------------------------------------------------------
// Kernel 2: kv[bh,c,d] += sum_{chunk} k*v ; ksum fused. grid (192, 8).
// ---------------------------------------------------------------------------
__global__ __launch_bounds__(256) void kv_kernel()
{
    const int bh   = blockIdx.x;
    const int j0s  = blockIdx.y * 512;
    const int tid  = threadIdx.x;
    const int d    = tid & 31;
    const int gr   = tid >> 5;
    const int cbase = gr * 4;
    __shared__ float sk[64 * 32];
    __shared__ float sv[64 * 32];
    __shared__ float sred[256];
    const size_t base = (size_t)bh * NTOK * HD;
    float acc[4] = {0.f, 0.f, 0.f, 0.f};
    float ksacc = 0.f;

    for (int j0 = j0s; j0 < j0s + 512; j0 += 64) {
        for (int i = tid; i < 512; i += 256) {
            const size_t gi = base + (size_t)j0 * HD + i * 4;
            float2 k01 = __half22float2(*(const __half2*)&g_kh[gi]);
            float2 k23 = __half22float2(*(const __half2*)&g_kh[gi + 2]);
            float2 v01 = __half22float2(*(const __half2*)&g_vh[gi]);
            float2 v23 = __half22float2(*(const __half2*)&g_vh[gi + 2]);
            *(float4*)&sk[i * 4] = make_float4(k01.x, k01.y, k23.x, k23.y);
            *(float4*)&sv[i * 4] = make_float4(v01.x, v01.y, v23.x, v23.y);
        }
        __syncthreads();
#pragma unroll 8
        for (int r = 0; r < 64; r++) {
            const float vv = sv[r * 32 + d];
#pragma unroll
            for (int q = 0; q < 4; q++) acc[q] += sk[r * 32 + cbase + q] * vv;
        }
#pragma unroll
        for (int r = 0; r < 8; r++) ksacc += sk[(gr + r * 8) * 32 + d];
        __syncthreads();
    }
#pragma unroll
    for (int q = 0; q < 4; q++)
        atomicAdd(&g_kv[bh * (HD * HD) + (cbase + q) * HD + d], acc[q]);

    sred[tid] = ksacc;
    __syncthreads();
    if (gr == 0) {
        float ssum = 0.f;
#pragma unroll
        for (int gg = 0; gg < 8; gg++) ssum += sred[gg * 32 + d];
        atomicAdd(&g_ksum[bh * HD + d], ssum);
    }
}

// ---------------------------------------------------------------------------
// Kernel 4: attn_out. Block = one y-row (64 tokens x 32 ch) of one bh.
// v conv tile staged as fp16 in smem; conv weights read from smem (d*25+k,
// 25 odd -> conflict-free). launch_bounds(256,4) for 4 blocks/SM.
// ---------------------------------------------------------------------------
#define SV_ROW (68 * 32)
// bytes: sv half 5*SV_ROW*2 = 21760; sq 2048*4; skv 1024*4; sw 800*4; sks 32*4
#define ATTN_SMEM (5*SV_ROW*2 + (2048 + 1024 + 800 + 32) * 4)

__global__ __launch_bounds__(256, 4) void attn_out(const float* __restrict__ dwc_w,
                                                   const float* __restrict__ dwc_b)
{
    extern __shared__ float sm[];
    __half* svh = (__half*)sm;                  // 5 * SV_ROW halfs (21760 B)
    float* sq  = sm + (5 * SV_ROW * 2) / 4;     // 2048 floats
    float* skv = sq + 2048;                     // 1024
    float* sw  = skv + 1024;                    // 800
    float* sks = sw + 800;                      // 32

    const int y  = blockIdx.x;
    const int bh = blockIdx.y;
    const int tid = threadIdx.x;
    const int d  = tid & 31;
    const int gr = tid >> 5;
    const int x0 = gr * 8;
    const size_t base = (size_t)bh * NTOK * HD;

    // zero x-halo columns (x = 0,1,66,67) of all 5 rows
    for (int i = tid; i < 5 * 4 * 32; i += 256) {
        const int row = i >> 7;
        const int rem = i & 127;
        const int col = rem >> 5;
        const int dd  = rem & 31;
        const int xc  = (col < 2) ? col : (64 + col);
        svh[row * SV_ROW + xc * 32 + dd] = __float2half(0.f);
    }
    // 5 input rows of v (raw fp16 copy; zero OOB rows)
#pragma unroll
    for (int ky = 0; ky < 5; ky++) {
        const int yy = y + ky - 2;
        for (int c = tid; c < 512; c += 256) {
            const int x = c >> 3, dq = (c & 7) * 4;
            uint2 val = make_uint2(0u, 0u);
            if ((unsigned)yy < 64u)
                val = *(const uint2*)&g_vh[base + ((size_t)(yy * 64 + x)) * HD + dq];
            *(uint2*)&svh[ky * SV_ROW + (x + 2) * 32 + dq] = val;
        }
    }
    // q row (fp32 in smem)
    for (int c = tid; c < 512; c += 256) {
        const int x = c >> 3, dq = (c & 7) * 4;
        const size_t gi = base + ((size_t)(y * 64 + x)) * HD + dq;
        float2 a = __half22float2(*(const __half2*)&g_qh[gi]);
        float2 bq = __half22float2(*(const __half2*)&g_qh[gi + 2]);
        *(float4*)&sq[x * 32 + dq] = make_float4(a.x, a.y, bq.x, bq.y);
    }
    // kv, weights, ksum
    *(float4*)&skv[tid * 4] = *(const float4*)&g_kv[bh * 1024 + tid * 4];
    for (int i = tid; i < 800; i += 256) sw[i] = dwc_w[i];
    if (tid < 32) sks[tid] = g_ksum[bh * HD + tid];
    __syncthreads();

    float rkv[32];
#pragma unroll
    for (int c = 0; c < 32; c++) rkv[c] = skv[c * 32 + d];
    const float rks = sks[d];
    const float rb  = dwc_b[d];

    // depthwise 5x5, 8 outputs per thread, sliding window; weights from smem
    float acc[8];
#pragma unroll
    for (int xi = 0; xi < 8; xi++) acc[xi] = rb;
#pragma unroll
    for (int ky = 0; ky < 5; ky++) {
        float w[12];
#pragma unroll
        for (int j = 0; j < 12; j++)
            w[j] = __half2float(svh[ky * SV_ROW + (x0 + j) * 32 + d]);
#pragma unroll
        for (int kx = 0; kx < 5; kx++) {
            const float cf = sw[d * 25 + ky * 5 + kx];
#pragma unroll
            for (int xi = 0; xi < 8; xi++) acc[xi] += cf * w[xi + kx];
        }
    }

    const int b_ = bh / HEADS, h = bh % HEADS;
#pragma unroll
    for (int xi = 0; xi < 8; xi++) {
        const int tok = x0 + xi;
        float o = 0.f;
#pragma unroll
        for (int c = 0; c < 32; c++) o += sq[tok * 32 + c] * rkv[c];
        float p = sq[tok * 32 + d] * rks;
#pragma unroll
        for (int off = 16; off; off >>= 1) p += __shfl_xor_sync(0xffffffffu, p, off);
        const float z = 1.f / (p + EPS);
        const int n = y * 64 + tok;
        g_preh[((size_t)(b_ * NTOK + n)) * CDIM + h * HD + d] =
            __float2half_rn(o * z + acc[xi]);
    }
}

// ---------------------------------------------------------------------------
// Kernel 5: proj GEMM (M=65536, Nout=384, K=384) + bias -> out (fp32).
// ---------------------------------------------------------------------------
__global__ __launch_bounds__(256) void proj_gemm(const float* __restrict__ bias,
                                                 float* __restrict__ out)
{
    GEMM_PROLOGUE(g_preh, g_wproj)
    GEMM_MAINLOOP(g_preh, g_wproj)

#pragma unroll
    for (int mt = 0; mt < 4; mt++) {
#pragma unroll
        for (int nt = 0; nt < 4; nt++) {
            const int j = jB + wN + nt * 8 + 2 * t;
            const float b0 = bias[j], b1 = bias[j + 1];
#pragma unroll
            for (int hh = 0; hh < 2; hh++) {
                const int m = mB + wM + mt * 16 + g + hh * 8;
                *(float2*)&out[(size_t)m * CDIM + j] =
                    make_float2(acc[mt][nt][hh * 2 + 0] + b0,
                                acc[mt][nt][hh * 2 + 1] + b1);
            }
        }
    }
}

// ---------------------------------------------------------------------------
extern "C" void kernel_launch(void* const* d_in, const int* in_sizes, int n_in,
                              void* d_out, int out_size)
{
    const float* x      = (const float*)d_in[0];
    const float* qkv_w  = (const float*)d_in[1];
    const float* pos    = (const float*)d_in[2];
    const float* dwc_w  = (const float*)d_in[3];
    const float* dwc_b  = (const float*)d_in[4];
    const float* proj_w = (const float*)d_in[5];
    const float* proj_b = (const float*)d_in[6];
    float* out = (float*)d_out;

    cudaFuncSetAttribute(attn_out, cudaFuncAttributeMaxDynamicSharedMemorySize, ATTN_SMEM);

    cvt_x<<<24576, 256>>>((const float4*)x);
    cvt_w<<<2304, 256>>>(qkv_w, proj_w);

    dim3 g1(9, M_TOT / 128);              // 1152/128 x 512
    qkv_gemm<<<g1, 256, GEMM_SMEM>>>(pos);

    zero_kv<<<(BH_TOT * HD * HD + 255) / 256, 256>>>();

    dim3 g3(BH_TOT, 8);
    kv_kernel<<<g3, 256>>>();

    dim3 g4(64, BH_TOT);
    attn_out<<<g4, 256, ATTN_SMEM>>>(dwc_w, dwc_b);

    dim3 g5(3, M_TOT / 128);              // 384/128 x 512
    proj_gemm<<<g5, 256, GEMM_SMEM>>>(proj_b, out);
}